// round 6
// baseline (speedup 1.0000x reference)
#include <cuda_runtime.h>

#define Bn 8
#define Cn 24
#define Mn 960
#define Wn 15                   // 64-bit words per row (960/64)
#define ROWS (Bn*Mn)            // 7680
#define NW (ROWS*Wn)            // 115200 words

typedef unsigned long long u64;

// Global bitmap planes: frontier (r=0) + 6 hrode planes r = 4,6,7,8,9,10.
__device__ u64 g_F[NW];
__device__ u64 g_P[6][NW];

// ── K1: pack + horizontal erosion (row-local, no halo, DRAM-streaming).
#define PR 16                   // rows per block
__global__ void __launch_bounds__(256) pack_kernel(const float* __restrict__ in) {
    __shared__ u64 sF[PR][Wn];
    const int lane = threadIdx.x & 31;
    const int warp = threadIdx.x >> 5;
    const int row0 = blockIdx.x * PR;                 // global row = b*Mn + y

#pragma unroll
    for (int i = 0; i < PR / 8; i++) {                // 8 warps, 2 rows each
        int rr = warp + (i << 3);
        int row = row0 + rr;
        int b = row / Mn, y = row - b * Mn;
        const float* p = in + ((size_t)(b * Cn + 1) * Mn + y) * Mn + lane;
        float v[30];
#pragma unroll
        for (int j = 0; j < 30; j++) v[j] = p[j * 32];
        unsigned bb[30];
#pragma unroll
        for (int j = 0; j < 30; j++) bb[j] = __ballot_sync(0xffffffffu, v[j] == 0.0f);
        if (lane < Wn) {
            unsigned lo = 0, hi = 0;
#pragma unroll
            for (int k = 0; k < Wn; k++)
                if (lane == k) { lo = bb[2 * k]; hi = bb[2 * k + 1]; }
            sF[rr][lane] = ((u64)hi << 32) | lo;
        }
    }
    __syncthreads();

    int t = threadIdx.x;
    if (t < PR * Wn) {                                // 240 words
        int rr = t / Wn, w = t - rr * Wn;
        u64 c = sF[rr][w];
        u64 l = (w > 0)      ? sF[rr][w - 1] : 0ULL;
        u64 r = (w < Wn - 1) ? sF[rr][w + 1] : 0ULL;
        int i = (row0 + rr) * Wn + w;
        g_F[i] = c;
        u64 acc = c;
#pragma unroll
        for (int d = 1; d <= 10; d++) {
            acc &= ((c << d) | (l >> (64 - d))) & ((c >> d) | (r << (64 - d)));
            if (d == 4)       g_P[0][i] = acc;
            else if (d == 6)  g_P[1][i] = acc;
            else if (d == 7)  g_P[2][i] = acc;
            else if (d == 8)  g_P[3][i] = acc;
            else if (d == 9)  g_P[4][i] = acc;
            else if (d == 10) g_P[5][i] = acc;
        }
    }
}

// ── K2: vertical 21-term AND computed for ROW PAIRS (34 shared loads per pair,
// exploiting erosion nesting P10 ⊆ P9 ⊆ ... ⊆ F), then border + float4 expand.
#define RB 32                   // output rows per block; grid = 240
__global__ void __launch_bounds__(256) morph_kernel(float* __restrict__ out) {
    __shared__ u64 sE[RB + 2][Wn];                    // 34 eroded rows
    __shared__ u64 sB[RB][Wn];
    const int t  = threadIdx.x;
    const int r0 = blockIdx.x * RB;
    const int b  = r0 / Mn;
    const int y0 = r0 - b * Mn;

    // Phase B: each thread computes TWO adjacent eroded rows at one word.
    // 17 pairs x 15 words = 255 tasks.
    if (t < ((RB + 2) / 2) * Wn) {
        int p = t / Wn, w = t - p * Wn;
        int yA = y0 - 1 + 2 * p;                      // first eroded row of pair
        auto idx = [&](int yy) {
            yy = yy < 0 ? 0 : (yy > Mn - 1 ? Mn - 1 : yy);
            return (b * Mn + yy) * Wn + w;
        };
        // Shared terms (valid for both rows; extras are supersets of kept terms)
        u64 s = g_P[4][idx(yA-3)] & g_P[4][idx(yA-2)] & g_P[4][idx(yA-1)] & g_P[4][idx(yA)]
              & g_P[4][idx(yA+1)] & g_P[4][idx(yA+2)] & g_P[4][idx(yA+3)] & g_P[4][idx(yA+4)];
        s &= g_P[3][idx(yA-5)] & g_P[3][idx(yA-4)] & g_P[3][idx(yA+5)] & g_P[3][idx(yA+6)];
        s &= g_P[2][idx(yA-6)] & g_P[2][idx(yA+7)];
        s &= g_P[1][idx(yA-7)] & g_P[1][idx(yA+8)];
        s &= g_P[0][idx(yA-8)] & g_P[0][idx(yA+9)];
        s &= g_F[idx(yA-9)]    & g_F[idx(yA+10)];
        u64 e0 = s & g_P[5][idx(yA)]   & g_P[4][idx(yA-4)] & g_P[3][idx(yA-6)]
                   & g_P[2][idx(yA-7)] & g_P[1][idx(yA-8)] & g_P[0][idx(yA-9)]
                   & g_F[idx(yA-10)];
        u64 e1 = s & g_P[5][idx(yA+1)] & g_P[4][idx(yA+5)] & g_P[3][idx(yA+7)]
                   & g_P[2][idx(yA+8)] & g_P[1][idx(yA+9)] & g_P[0][idx(yA+10)]
                   & g_F[idx(yA+11)];
        sE[2*p][w]     = (yA     >= 10 && yA     <= Mn - 11) ? e0 : 0ULL;
        sE[2*p + 1][w] = (yA + 1 >= 10 && yA + 1 <= Mn - 11) ? e1 : 0ULL;
    }
    __syncthreads();

    // Phase C: border = dilate(e, cross) & ~e (480 tasks, 2 per thread)
#pragma unroll
    for (int q = 0; q < 2; q++) {
        int task = t + (q << 8);
        if (task < RB * Wn) {
            int rr = task / Wn, w = task - rr * Wn;
            u64 e  = sE[rr + 1][w];
            u64 eu = sE[rr][w];
            u64 ed = sE[rr + 2][w];
            u64 l  = (w > 0)      ? sE[rr + 1][w - 1] : 0ULL;
            u64 r  = (w < Wn - 1) ? sE[rr + 1][w + 1] : 0ULL;
            u64 d = e | eu | ed | (e << 1) | (l >> 63) | (e >> 1) | (r << 63);
            sB[rr][w] = d & ~e;
        }
    }
    __syncthreads();

    // Phase D: bits -> float4, coalesced stores (RB*240 = 7680 chunks, 30/thread)
    float4* o = (float4*)out + (size_t)r0 * (Mn / 4);
#pragma unroll
    for (int k = 0; k < (RB * (Mn / 4)) / 256; k++) {
        int c = t + (k << 8);
        int rr = c / (Mn / 4), cc = c - rr * (Mn / 4);
        u64 bw = sB[rr][cc >> 4];
        unsigned nib = (unsigned)(bw >> ((cc & 15) << 2)) & 15u;
        o[c] = make_float4(nib & 1u ? 1.0f : 0.0f, nib & 2u ? 1.0f : 0.0f,
                           nib & 4u ? 1.0f : 0.0f, nib & 8u ? 1.0f : 0.0f);
    }
}

extern "C" void kernel_launch(void* const* d_in, const int* in_sizes, int n_in,
                              void* d_out, int out_size) {
    const float* map_features = (const float*)d_in[0];
    float* out = (float*)d_out;
    pack_kernel<<<ROWS / PR, 256>>>(map_features);    // 480 blocks
    morph_kernel<<<ROWS / RB, 256>>>(out);            // 240 blocks
}

// round 7
// speedup vs baseline: 1.1336x; 1.1336x over previous
#include <cuda_runtime.h>

#define Bn 8
#define Cn 24
#define Mn 960
#define Wn 15                   // 64-bit words per row (960/64)
#define ROWS (Bn*Mn)            // 7680
#define NW (ROWS*Wn)            // 115200 words

typedef unsigned long long u64;

// Global bitmap planes: frontier (r=0) + 6 hrode planes r = 4,6,7,8,9,10.
__device__ u64 g_F[NW];
__device__ u64 g_P[6][NW];

// ── K1: pack + horizontal erosion (row-local, no halo, DRAM-streaming).
#define PR 16                   // rows per block
__global__ void __launch_bounds__(256) pack_kernel(const float* __restrict__ in) {
    __shared__ u64 sF[PR][Wn];
    const int lane = threadIdx.x & 31;
    const int warp = threadIdx.x >> 5;
    const int row0 = blockIdx.x * PR;                 // global row = b*Mn + y

#pragma unroll
    for (int i = 0; i < PR / 8; i++) {                // 8 warps, 2 rows each
        int rr = warp + (i << 3);
        int row = row0 + rr;
        int b = row / Mn, y = row - b * Mn;
        const float* p = in + ((size_t)(b * Cn + 1) * Mn + y) * Mn + lane;
        float v[30];
#pragma unroll
        for (int j = 0; j < 30; j++) v[j] = p[j * 32];
        unsigned bb[30];
#pragma unroll
        for (int j = 0; j < 30; j++) bb[j] = __ballot_sync(0xffffffffu, v[j] == 0.0f);
        if (lane < Wn) {
            unsigned lo = 0, hi = 0;
#pragma unroll
            for (int k = 0; k < Wn; k++)
                if (lane == k) { lo = bb[2 * k]; hi = bb[2 * k + 1]; }
            sF[rr][lane] = ((u64)hi << 32) | lo;
        }
    }
    __syncthreads();

    int t = threadIdx.x;
    if (t < PR * Wn) {                                // 240 words
        int rr = t / Wn, w = t - rr * Wn;
        u64 c = sF[rr][w];
        u64 l = (w > 0)      ? sF[rr][w - 1] : 0ULL;
        u64 r = (w < Wn - 1) ? sF[rr][w + 1] : 0ULL;
        int i = (row0 + rr) * Wn + w;
        g_F[i] = c;
        u64 acc = c;
#pragma unroll
        for (int d = 1; d <= 10; d++) {
            acc &= ((c << d) | (l >> (64 - d))) & ((c >> d) | (r << (64 - d)));
            if (d == 4)       g_P[0][i] = acc;
            else if (d == 6)  g_P[1][i] = acc;
            else if (d == 7)  g_P[2][i] = acc;
            else if (d == 8)  g_P[3][i] = acc;
            else if (d == 9)  g_P[4][i] = acc;
            else if (d == 10) g_P[5][i] = acc;
        }
    }
}

// ── K2: vertical 21-term AND -> border -> float4 expand.
// 160 threads: phase B = 150 tasks (1/thread), phase D = 12 exact iterations.
// launch_bounds(160,5) gives ~81 regs/thread so all 21 loads stay in flight.
#define RB 8                    // output rows per block; grid = 960
#define NT 160
__global__ void __launch_bounds__(NT, 5) morph_kernel(float* __restrict__ out) {
    __shared__ u64 sE[RB + 2][Wn];
    __shared__ u64 sB[RB][Wn];
    const int t  = threadIdx.x;
    const int r0 = blockIdx.x * RB;
    const int b  = r0 / Mn;
    const int y0 = r0 - b * Mn;

    // Phase B: eroded rows y0-1 .. y0+RB (±1 halo), 150 tasks.
    if (t < (RB + 2) * Wn) {
        int rr = t / Wn, w = t - rr * Wn;
        int y = y0 + rr - 1;
        u64 e = 0ULL;
        if (y >= 10 && y <= Mn - 11) {
            int i = (b * Mn + y) * Wn + w;
            u64 v[21];
            v[0]  = g_P[5][i];
            v[1]  = g_P[4][i - 1*Wn];  v[2]  = g_P[4][i + 1*Wn];
            v[3]  = g_P[4][i - 2*Wn];  v[4]  = g_P[4][i + 2*Wn];
            v[5]  = g_P[4][i - 3*Wn];  v[6]  = g_P[4][i + 3*Wn];
            v[7]  = g_P[4][i - 4*Wn];  v[8]  = g_P[4][i + 4*Wn];
            v[9]  = g_P[3][i - 5*Wn];  v[10] = g_P[3][i + 5*Wn];
            v[11] = g_P[3][i - 6*Wn];  v[12] = g_P[3][i + 6*Wn];
            v[13] = g_P[2][i - 7*Wn];  v[14] = g_P[2][i + 7*Wn];
            v[15] = g_P[1][i - 8*Wn];  v[16] = g_P[1][i + 8*Wn];
            v[17] = g_P[0][i - 9*Wn];  v[18] = g_P[0][i + 9*Wn];
            v[19] = g_F[i - 10*Wn];    v[20] = g_F[i + 10*Wn];
            // balanced reduction tree
            u64 a0 = (v[0] & v[1]) & (v[2] & v[3]);
            u64 a1 = (v[4] & v[5]) & (v[6] & v[7]);
            u64 a2 = (v[8] & v[9]) & (v[10] & v[11]);
            u64 a3 = (v[12] & v[13]) & (v[14] & v[15]);
            u64 a4 = (v[16] & v[17]) & (v[18] & v[19]);
            e = ((a0 & a1) & (a2 & a3)) & (a4 & v[20]);
        }
        sE[rr][w] = e;
    }
    __syncthreads();

    // Phase C: border = dilate(e, cross) & ~e, 120 tasks.
    if (t < RB * Wn) {
        int rr = t / Wn, w = t - rr * Wn;
        u64 e  = sE[rr + 1][w];
        u64 eu = sE[rr][w];
        u64 ed = sE[rr + 2][w];
        u64 l  = (w > 0)      ? sE[rr + 1][w - 1] : 0ULL;
        u64 r  = (w < Wn - 1) ? sE[rr + 1][w + 1] : 0ULL;
        u64 d = e | eu | ed | (e << 1) | (l >> 63) | (e >> 1) | (r << 63);
        sB[rr][w] = d & ~e;
    }
    __syncthreads();

    // Phase D: bits -> float4, coalesced stores (1920 chunks, 12/thread exact).
    float4* o = (float4*)out + (size_t)r0 * (Mn / 4);
#pragma unroll
    for (int k = 0; k < (RB * (Mn / 4)) / NT; k++) {
        int c = t + k * NT;
        int rr = c / (Mn / 4), cc = c - rr * (Mn / 4);
        u64 bw = sB[rr][cc >> 4];
        unsigned nib = (unsigned)(bw >> ((cc & 15) << 2)) & 15u;
        o[c] = make_float4(nib & 1u ? 1.0f : 0.0f, nib & 2u ? 1.0f : 0.0f,
                           nib & 4u ? 1.0f : 0.0f, nib & 8u ? 1.0f : 0.0f);
    }
}

extern "C" void kernel_launch(void* const* d_in, const int* in_sizes, int n_in,
                              void* d_out, int out_size) {
    const float* map_features = (const float*)d_in[0];
    float* out = (float*)d_out;
    pack_kernel<<<ROWS / PR, 256>>>(map_features);    // 480 blocks
    morph_kernel<<<ROWS / RB, NT>>>(out);             // 960 blocks
}